// round 11
// baseline (speedup 1.0000x reference)
#include <cuda_runtime.h>
#include <cuda_fp16.h>
#include <cstdint>

#define BB 8
#define NN 4096
#define EE 2048
#define CC 128

// ---------------- device scratch ----------------
__device__ __half g_hh [BB*NN*EE];    // H in fp16 (written by v2e, read by e2v)
__device__ __half g_efh[BB*EE*CC];    // post-fc normalized edge feats, fp16
__device__ __half g_xh [BB*NN*CC];    // x in fp16
__device__ __half g_wh [CC*CC];       // W in fp16

__device__ __forceinline__ uint2 f4h(float4 v){
    __half2 a = __floats2half2_rn(v.x, v.y);
    __half2 b = __floats2half2_rn(v.z, v.w);
    uint2 r;
    r.x = *reinterpret_cast<uint32_t*>(&a);
    r.y = *reinterpret_cast<uint32_t*>(&b);
    return r;
}
__device__ __forceinline__ __half2 u2h(uint32_t u){ return *reinterpret_cast<__half2*>(&u); }

__device__ __forceinline__ void cpa16(uint32_t dst, const void* src){
    asm volatile("cp.async.cg.shared.global [%0], [%1], 16;\n" :: "r"(dst), "l"(src));
}
__device__ __forceinline__ void cp_commit(){ asm volatile("cp.async.commit_group;\n"); }

__device__ __forceinline__ void ldsm4(uint32_t* r, uint32_t a){
    asm volatile("ldmatrix.sync.aligned.m8n8.x4.shared.b16 {%0,%1,%2,%3}, [%4];"
                 : "=r"(r[0]),"=r"(r[1]),"=r"(r[2]),"=r"(r[3]) : "r"(a));
}
__device__ __forceinline__ void ldsm4t(uint32_t* r, uint32_t a){
    asm volatile("ldmatrix.sync.aligned.m8n8.x4.trans.shared.b16 {%0,%1,%2,%3}, [%4];"
                 : "=r"(r[0]),"=r"(r[1]),"=r"(r[2]),"=r"(r[3]) : "r"(a));
}
__device__ __forceinline__ void mma16(float* c, const uint32_t* a, const uint32_t* b){
    asm volatile(
        "mma.sync.aligned.m16n8k16.row.col.f32.f16.f16.f32 "
        "{%0,%1,%2,%3}, {%4,%5,%6,%7}, {%8,%9}, {%0,%1,%2,%3};"
        : "+f"(c[0]),"+f"(c[1]),"+f"(c[2]),"+f"(c[3])
        : "r"(a[0]),"r"(a[1]),"r"(a[2]),"r"(a[3]),"r"(b[0]),"r"(b[1]));
}

// ---------------- prep: fp16-convert x and W ----------------
__global__ void prep_kernel(const float* __restrict__ x, const float* __restrict__ W){
    const int NX4 = BB*NN*CC/4, NW4 = CC*CC/4;
    int i = blockIdx.x*256 + threadIdx.x;
    if (i < NX4){
        ((uint2*)g_xh)[i] = f4h(((const float4*)x)[i]);
    } else if (i - NX4 < NW4){
        ((uint2*)g_wh)[i-NX4] = f4h(((const float4*)W)[i-NX4]);
    }
}

// ================= v2e + fc fused (BM=64, K=4096) + H transcode =================
#define LDH 136                  // halves; [k][*] row stride (17x16B, ldmatrix conflict-free)
#define A0_BYTES (32*LDH*2)      // 8704
#define B_BYTES  (32*LDH*2)      // 8704
#define STB0     (A0_BYTES + B_BYTES)
#define LDMK 40                  // halves; [m][k=32] chunk row stride (5x16B)
#define LDFA 136                 // halves; fc A-tile [m=64][k=128] row stride
#define FC_A_OFF 0               // fc A_sm: 64*LDFA*2 = 17408 B
#define FC_W_OFF 17408           // fc W tile: 128*LDH*2 = 34816 B -> ends at 52224

__global__ void __launch_bounds__(256,2)
v2e_fc_kernel(const float* __restrict__ H, const float* __restrict__ bias)
{
    constexpr int CHUNKS = NN/32;   // 128
    extern __shared__ char smraw[];
    __shared__ float deg_s[64];

    const int t=threadIdx.x, lane=t&31, wid=t>>5;
    const int b=blockIdx.y, m0g=blockIdx.x*64;
    const int wm=wid&1, wn=wid>>1;          // 2 row-groups x 4 col-groups of 32
    const int gid=lane>>2, tig=lane&3;
    const int grp=lane>>3, gj=lane&7;

    const float* __restrict__ Hb = H + (size_t)b*NN*EE;
    const uint32_t smb = (uint32_t)__cvta_generic_to_shared(smraw);

    float acc[2][4][4];
#pragma unroll
    for (int i=0;i<2;i++)
#pragma unroll
        for (int j=0;j<4;j++)
#pragma unroll
            for (int r=0;r<4;r++) acc[i][j][r]=0.f;
    __half2 dg2[2][2];
    dg2[0][0]=dg2[0][1]=dg2[1][0]=dg2[1][1]=__floats2half2_rn(0.f,0.f);

    const int a_k  = ((grp&2)?8:0) + gj;   // trans A k-offset
    const int a_m0 = ((grp&1)?8:0);        // trans A m-offset
    const int a_r  = ((grp&1)?8:0) + gj;   // non-trans A m-offset (fc)
    const int a_c  = ((grp&2)?8:0);        // non-trans A k-offset (fc)
    const int b_r  = ((grp&1)?8:0) + gj;   // B k-offset
    const int b_c  = (grp>>1)*8;           // B n-offset

    auto ldgA = [&](int kc, float4* r){
        const int kg0 = kc*32;
#pragma unroll
        for (int i=0;i<2;i++){
            const int idx = t + 256*i;
            const int k = idx>>4, m4 = (idx&15)*4;
            r[i] = *(const float4*)(Hb + (size_t)(kg0+k)*EE + m0g + m4);
        }
    };
    auto stsA = [&](int kc, const float4* r, int buf){
        const int kg0 = kc*32;
        const uint32_t aB = smb + (uint32_t)(buf*STB0);
#pragma unroll
        for (int i=0;i<2;i++){
            const int idx = t + 256*i;
            const int k = idx>>4, m4 = (idx&15)*4;
            uint2 h = f4h(r[i]);
            asm volatile("st.shared.v2.b32 [%0], {%1,%2};"
                         :: "r"(aB + (uint32_t)((k*LDH + m4)*2)), "r"(h.x), "r"(h.y));
            *(uint2*)&g_hh[((size_t)b*NN + kg0 + k)*EE + m0g + m4] = h;  // H transcode
        }
    };
    auto stageB = [&](int kc, int buf){
        const int kg0 = kc*32;
        const uint32_t bB = smb + (uint32_t)(buf*STB0 + A0_BYTES);
        const __half* src0 = g_xh + ((size_t)b*NN + kg0)*CC;
#pragma unroll
        for (int i=0;i<2;i++){
            const int idx = t + 256*i;
            const int k = idx>>4, n8 = (idx&15)*8;
            cpa16(bB + (uint32_t)((k*LDH + n8)*2), src0 + (size_t)k*CC + n8);
        }
    };

    auto compute = [&](int buf){
        const uint32_t aB = smb + (uint32_t)(buf*STB0);
        const uint32_t bB = aB + (uint32_t)A0_BYTES;
#pragma unroll
        for (int s=0;s<2;s++){
            const int k0 = s*16;
            uint32_t a[2][4], bf[4][2];
#pragma unroll
            for (int mt=0;mt<2;mt++)
                ldsm4t(a[mt], aB + (uint32_t)(((k0 + a_k)*LDH + wm*32 + mt*16 + a_m0)*2));
            if (wn==0){
#pragma unroll
                for (int mt=0;mt<2;mt++){
                    dg2[mt][0] = __hadd2(dg2[mt][0], __hadd2(u2h(a[mt][0]), u2h(a[mt][2])));
                    dg2[mt][1] = __hadd2(dg2[mt][1], __hadd2(u2h(a[mt][1]), u2h(a[mt][3])));
                }
            }
#pragma unroll
            for (int p=0;p<2;p++){
                uint32_t r[4];
                ldsm4t(r, bB + (uint32_t)(((k0 + b_r)*LDH + wn*32 + p*16 + b_c)*2));
                bf[2*p  ][0]=r[0]; bf[2*p  ][1]=r[1];
                bf[2*p+1][0]=r[2]; bf[2*p+1][1]=r[3];
            }
#pragma unroll
            for (int mt=0;mt<2;mt++)
#pragma unroll
                for (int j=0;j<4;j++)
                    mma16(acc[mt][j], a[mt], bf[j]);
        }
    };

    float4 rA[2];
    ldgA(0,rA); stsA(0,rA,0); stageB(0,0); cp_commit();
    ldgA(1,rA); stsA(1,rA,1); stageB(1,1); cp_commit();
    for (int kc=0; kc<CHUNKS; kc++){
        asm volatile("cp.async.wait_group 1;" ::: "memory");
        __syncthreads();
        const bool pre = (kc+2 < CHUNKS);
        if (pre){ ldgA(kc+2,rA); stageB(kc+2,(kc+2)%3); }
        cp_commit();
        compute(kc%3);
        if (pre) stsA(kc+2,rA,(kc+2)%3);
    }
    asm volatile("cp.async.wait_group 0;" ::: "memory");
    __syncthreads();   // mainloop buffers now dead; smem reused for fc

    // ---- stage W tile [k=128][n=128] ----
    {
        const uint32_t wB = smb + FC_W_OFF;
        const __half* src0 = g_wh;
#pragma unroll
        for (int i=0;i<8;i++){
            const int idx = t + 256*i;
            const int k = idx>>4, n8 = (idx&15)*8;
            cpa16(wB + (uint32_t)((k*LDH + n8)*2), src0 + (size_t)k*CC + n8);
        }
        cp_commit();
    }

    // ---- edge degrees -> deg_s ----
#pragma unroll
    for (int mt=0;mt<2;mt++)
#pragma unroll
        for (int rh=0;rh<2;rh++){
            float2 f = __half22float2(dg2[mt][rh]);
            float v = f.x + f.y;
            v += __shfl_xor_sync(0xffffffffu, v, 1);
            v += __shfl_xor_sync(0xffffffffu, v, 2);
            if (wn==0 && tig==0)
                deg_s[wm*32+mt*16+rh*8+gid] = v;
        }
    __syncthreads();

    // ---- store normalized fp16 A-tile [m=64][k=128], stride LDFA ----
    {
        const uint32_t aS = smb + FC_A_OFF;
#pragma unroll
        for (int mt=0;mt<2;mt++)
#pragma unroll
            for (int rh=0;rh<2;rh++){
                const int row = wm*32+mt*16+rh*8+gid;
                const float d = deg_s[row];
                const float inv = (d > 0.f) ? 1.f/d : 0.f;
#pragma unroll
                for (int j=0;j<4;j++){
                    const int col = wn*32 + j*8 + tig*2;
                    __half2 h = __floats2half2_rn(acc[mt][j][rh*2]*inv, acc[mt][j][rh*2+1]*inv);
                    asm volatile("st.shared.b32 [%0], %1;"
                                 :: "r"(aS + (uint32_t)((row*LDFA + col)*2)), "r"(*(uint32_t*)&h));
                }
            }
    }
    asm volatile("cp.async.wait_group 0;" ::: "memory");
    __syncthreads();

    // ---- fc GEMM: [64 x 128] = A_sm[64 x 128] @ W[128 x 128] ----
    float fcc[2][4][4];
#pragma unroll
    for (int i=0;i<2;i++)
#pragma unroll
        for (int j=0;j<4;j++)
#pragma unroll
            for (int r=0;r<4;r++) fcc[i][j][r]=0.f;
    {
        const uint32_t aS = smb + FC_A_OFF;
        const uint32_t wB = smb + FC_W_OFF;
#pragma unroll
        for (int ks=0; ks<8; ks++){
            const int k0 = ks*16;
            uint32_t a[2][4], bf[4][2];
#pragma unroll
            for (int mt=0;mt<2;mt++)
                ldsm4(a[mt], aS + (uint32_t)(((wm*32 + mt*16 + a_r)*LDFA + k0 + a_c)*2));
#pragma unroll
            for (int p=0;p<2;p++){
                uint32_t r[4];
                ldsm4t(r, wB + (uint32_t)(((k0 + b_r)*LDH + wn*32 + p*16 + b_c)*2));
                bf[2*p  ][0]=r[0]; bf[2*p  ][1]=r[1];
                bf[2*p+1][0]=r[2]; bf[2*p+1][1]=r[3];
            }
#pragma unroll
            for (int mt=0;mt<2;mt++)
#pragma unroll
                for (int j=0;j<4;j++)
                    mma16(fcc[mt][j], a[mt], bf[j]);
        }
    }

    // ---- +bias, mask, write g_efh ----
#pragma unroll
    for (int mt=0;mt<2;mt++)
#pragma unroll
        for (int rh=0;rh<2;rh++){
            const int row = wm*32+mt*16+rh*8+gid;
            const bool on = deg_s[row] > 0.f;
#pragma unroll
            for (int j=0;j<4;j++){
                const int col = wn*32 + j*8 + tig*2;
                float v0 = on ? fcc[mt][j][rh*2  ] + bias[col]   : 0.f;
                float v1 = on ? fcc[mt][j][rh*2+1] + bias[col+1] : 0.f;
                __half2 h = __floats2half2_rn(v0, v1);
                *(uint32_t*)&g_efh[((size_t)b*EE+m0g+row)*CC + col] = *(uint32_t*)&h;
            }
        }
}

// ================= e2v: pure cp.async fp16 GEMM, 5-stage =================
#define A_BYTES2 (128*LDMK*2)   // 10240
#define STB2     (A_BYTES2 + B_BYTES)
#define NSTAGE 5

__global__ void __launch_bounds__(256,2)
e2v_kernel(float* __restrict__ out)
{
    constexpr int CHUNKS = EE/32;   // 64

    extern __shared__ char smraw[];
    __shared__ float deg_s[128];

    const int t=threadIdx.x, lane=t&31, wid=t>>5;
    const int b=blockIdx.y, m0g=blockIdx.x*128;
    const int wm=wid>>1, wn=wid&1, gid=lane>>2, tig=lane&3;
    const int grp=lane>>3, gj=lane&7;

    const uint32_t smb = (uint32_t)__cvta_generic_to_shared(smraw);

    float acc[2][8][4];
#pragma unroll
    for (int i=0;i<2;i++)
#pragma unroll
        for (int j=0;j<8;j++)
#pragma unroll
            for (int r=0;r<4;r++) acc[i][j][r]=0.f;
    __half2 dg2[2][2];
    dg2[0][0]=dg2[0][1]=dg2[1][0]=dg2[1][1]=__floats2half2_rn(0.f,0.f);

    const int a_r = ((grp&1)?8:0) + gj;
    const int a_c = ((grp&2)?8:0);
    const int b_r = ((grp&1)?8:0) + gj;
    const int b_c = (grp>>1)*8;

    auto stage = [&](int kc, int buf){
        const int kg0 = kc*32;
        const uint32_t aB = smb + (uint32_t)(buf*STB2);
        const uint32_t bB = aB + (uint32_t)A_BYTES2;
        const __half* asrc = g_hh + ((size_t)b*NN + m0g)*EE + kg0;
#pragma unroll
        for (int i=0;i<2;i++){
            const int idx = t + 256*i;
            const int m = idx>>2, k8 = (idx&3)*8;
            cpa16(aB + (uint32_t)((m*LDMK + k8)*2), asrc + (size_t)m*EE + k8);
        }
        const __half* bsrc = g_efh + ((size_t)b*EE + kg0)*CC;
#pragma unroll
        for (int i=0;i<2;i++){
            const int idx = t + 256*i;
            const int k = idx>>4, n8 = (idx&15)*8;
            cpa16(bB + (uint32_t)((k*LDH + n8)*2), bsrc + (size_t)k*CC + n8);
        }
    };

    auto compute = [&](int buf){
        const uint32_t aB = smb + (uint32_t)(buf*STB2);
        const uint32_t bB = aB + (uint32_t)A_BYTES2;
#pragma unroll
        for (int s=0;s<2;s++){
            const int k0 = s*16;
            uint32_t a[2][4], bf[8][2];
#pragma unroll
            for (int mt=0;mt<2;mt++)
                ldsm4(a[mt], aB + (uint32_t)(((wm*32 + mt*16 + a_r)*LDMK + k0 + a_c)*2));
            if (wn==0){
#pragma unroll
                for (int mt=0;mt<2;mt++){
                    dg2[mt][0] = __hadd2(dg2[mt][0], __hadd2(u2h(a[mt][0]), u2h(a[mt][2])));
                    dg2[mt][1] = __hadd2(dg2[mt][1], __hadd2(u2h(a[mt][1]), u2h(a[mt][3])));
                }
            }
#pragma unroll
            for (int p=0;p<4;p++){
                uint32_t r[4];
                ldsm4t(r, bB + (uint32_t)(((k0 + b_r)*LDH + wn*64 + p*16 + b_c)*2));
                bf[2*p  ][0]=r[0]; bf[2*p  ][1]=r[1];
                bf[2*p+1][0]=r[2]; bf[2*p+1][1]=r[3];
            }
#pragma unroll
            for (int mt=0;mt<2;mt++)
#pragma unroll
                for (int j=0;j<8;j++)
                    mma16(acc[mt][j], a[mt], bf[j]);
        }
    };

#pragma unroll
    for (int s=0; s<NSTAGE-1; s++){
        if (s < CHUNKS) stage(s, s);
        cp_commit();
    }
    for (int kc=0; kc<CHUNKS; kc++){
        asm volatile("cp.async.wait_group %0;" :: "n"(NSTAGE-2) : "memory");
        __syncthreads();
        if (kc+NSTAGE-1 < CHUNKS) stage(kc+NSTAGE-1, (kc+NSTAGE-1)%NSTAGE);
        cp_commit();
        compute(kc%NSTAGE);
    }

    // node degrees from fragments
#pragma unroll
    for (int mt=0;mt<2;mt++)
#pragma unroll
        for (int rh=0;rh<2;rh++){
            float2 f = __half22float2(dg2[mt][rh]);
            float v = f.x + f.y;
            v += __shfl_xor_sync(0xffffffffu, v, 1);
            v += __shfl_xor_sync(0xffffffffu, v, 2);
            if (wn==0 && tig==0) deg_s[wm*32+mt*16+rh*8+gid] = v;
        }
    __syncthreads();

#pragma unroll
    for (int mt=0;mt<2;mt++)
#pragma unroll
        for (int rh=0;rh<2;rh++){
            const int row = wm*32+mt*16+rh*8+gid;
            const float d   = deg_s[row];
            const float inv = (d > 0.f) ? 1.f/d : 0.f;
#pragma unroll
            for (int j=0;j<8;j++){
                const int col = wn*64 + j*8 + tig*2;
                *(float2*)&out[((size_t)b*NN+m0g+row)*CC + col]
                    = make_float2(acc[mt][j][rh*2]*inv, acc[mt][j][rh*2+1]*inv);
            }
        }
}

// ---------------- launcher ----------------
extern "C" void kernel_launch(void* const* d_in, const int* in_sizes, int n_in,
                              void* d_out, int out_size)
{
    const float* x    = (const float*)d_in[0];
    const float* H    = (const float*)d_in[1];
    const float* W    = (const float*)d_in[2];
    const float* bias = (const float*)d_in[3];
    float* out = (float*)d_out;

    const int sm0 = 3*STB0;        // 52224 B (fc epilogue needs 52224 exactly)
    const int sm2 = NSTAGE*STB2;   // 94720 B
    cudaFuncSetAttribute(v2e_fc_kernel, cudaFuncAttributeMaxDynamicSharedMemorySize, sm0);
    cudaFuncSetAttribute(e2v_kernel,    cudaFuncAttributeMaxDynamicSharedMemorySize, sm2);

    const int prep_blk = (BB*NN*CC/4 + CC*CC/4 + 255)/256;

    prep_kernel  <<<prep_blk, 256>>>(x, W);
    v2e_fc_kernel<<<dim3(EE/64,  BB), 256, sm0>>>(H, bias);
    e2v_kernel   <<<dim3(NN/128, BB), 256, sm2>>>(out);
}

// round 12
// speedup vs baseline: 1.0255x; 1.0255x over previous
#include <cuda_runtime.h>
#include <cuda_fp16.h>
#include <cstdint>

#define BB 8
#define NN 4096
#define EE 2048
#define CC 128
#define EW (EE/32)   // 64 words per node row

// ---------------- device scratch ----------------
__device__ uint32_t g_hb [BB*NN*EW];  // H bit-packed, node-major (written by v2e)
__device__ __half   g_efh[BB*EE*CC];  // post-fc normalized edge feats, fp16
__device__ __half   g_xh [BB*NN*CC];  // x in fp16
__device__ __half   g_wh [CC*CC];     // W in fp16

__device__ __forceinline__ uint2 f4h(float4 v){
    __half2 a = __floats2half2_rn(v.x, v.y);
    __half2 b = __floats2half2_rn(v.z, v.w);
    uint2 r;
    r.x = *reinterpret_cast<uint32_t*>(&a);
    r.y = *reinterpret_cast<uint32_t*>(&b);
    return r;
}
__device__ __forceinline__ __half2 u2h(uint32_t u){ return *reinterpret_cast<__half2*>(&u); }

__device__ __forceinline__ void cpa16(uint32_t dst, const void* src){
    asm volatile("cp.async.cg.shared.global [%0], [%1], 16;\n" :: "r"(dst), "l"(src));
}
__device__ __forceinline__ void cp_commit(){ asm volatile("cp.async.commit_group;\n"); }

__device__ __forceinline__ void ldsm4(uint32_t* r, uint32_t a){
    asm volatile("ldmatrix.sync.aligned.m8n8.x4.shared.b16 {%0,%1,%2,%3}, [%4];"
                 : "=r"(r[0]),"=r"(r[1]),"=r"(r[2]),"=r"(r[3]) : "r"(a));
}
__device__ __forceinline__ void ldsm4t(uint32_t* r, uint32_t a){
    asm volatile("ldmatrix.sync.aligned.m8n8.x4.trans.shared.b16 {%0,%1,%2,%3}, [%4];"
                 : "=r"(r[0]),"=r"(r[1]),"=r"(r[2]),"=r"(r[3]) : "r"(a));
}
__device__ __forceinline__ void mma16(float* c, const uint32_t* a, const uint32_t* b){
    asm volatile(
        "mma.sync.aligned.m16n8k16.row.col.f32.f16.f16.f32 "
        "{%0,%1,%2,%3}, {%4,%5,%6,%7}, {%8,%9}, {%0,%1,%2,%3};"
        : "+f"(c[0]),"+f"(c[1]),"+f"(c[2]),"+f"(c[3])
        : "r"(a[0]),"r"(a[1]),"r"(a[2]),"r"(a[3]),"r"(b[0]),"r"(b[1]));
}

// ---------------- prep: fp16-convert x and W ----------------
__global__ void prep_kernel(const float* __restrict__ x, const float* __restrict__ W){
    const int NX4 = BB*NN*CC/4, NW4 = CC*CC/4;
    int i = blockIdx.x*256 + threadIdx.x;
    if (i < NX4){
        ((uint2*)g_xh)[i] = f4h(((const float4*)x)[i]);
    } else if (i - NX4 < NW4){
        ((uint2*)g_wh)[i-NX4] = f4h(((const float4*)W)[i-NX4]);
    }
}

// ================= v2e + fc fused (BM=64, K=4096) + H bit-pack =================
#define LDH 136                  // halves; [k][*] row stride (17x16B, ldmatrix conflict-free)
#define A0_BYTES (32*LDH*2)      // 8704
#define B_BYTES  (32*LDH*2)      // 8704
#define STB0     (A0_BYTES + B_BYTES)
#define LDMK 40                  // halves; [m][k=32] chunk row stride (5x16B)
#define LDFA 136                 // halves; fc A-tile [m=64][k=128] row stride
#define FC_A_OFF 0               // fc A_sm: 64*LDFA*2 = 17408 B
#define FC_W_OFF 17408           // fc W tile: 128*LDH*2 = 34816 B -> ends at 52224

__global__ void __launch_bounds__(256,2)
v2e_fc_kernel(const float* __restrict__ H, const float* __restrict__ bias)
{
    constexpr int CHUNKS = NN/32;   // 128
    extern __shared__ char smraw[];
    __shared__ float deg_s[64];

    const int t=threadIdx.x, lane=t&31, wid=t>>5;
    const int b=blockIdx.y, m0g=blockIdx.x*64;
    const int wm=wid&1, wn=wid>>1;          // 2 row-groups x 4 col-groups of 32
    const int gid=lane>>2, tig=lane&3;
    const int grp=lane>>3, gj=lane&7;

    const float* __restrict__ Hb = H + (size_t)b*NN*EE;
    const uint32_t smb = (uint32_t)__cvta_generic_to_shared(smraw);

    float acc[2][4][4];
#pragma unroll
    for (int i=0;i<2;i++)
#pragma unroll
        for (int j=0;j<4;j++)
#pragma unroll
            for (int r=0;r<4;r++) acc[i][j][r]=0.f;
    __half2 dg2[2][2];
    dg2[0][0]=dg2[0][1]=dg2[1][0]=dg2[1][1]=__floats2half2_rn(0.f,0.f);

    const int a_k  = ((grp&2)?8:0) + gj;   // trans A k-offset
    const int a_m0 = ((grp&1)?8:0);        // trans A m-offset
    const int a_r  = ((grp&1)?8:0) + gj;   // non-trans A m-offset (fc)
    const int a_c  = ((grp&2)?8:0);        // non-trans A k-offset (fc)
    const int b_r  = ((grp&1)?8:0) + gj;   // B k-offset
    const int b_c  = (grp>>1)*8;           // B n-offset

    auto ldgA = [&](int kc, float4* r){
        const int kg0 = kc*32;
#pragma unroll
        for (int i=0;i<2;i++){
            const int idx = t + 256*i;
            const int k = idx>>4, m4 = (idx&15)*4;
            r[i] = *(const float4*)(Hb + (size_t)(kg0+k)*EE + m0g + m4);
        }
    };
    auto stsA = [&](int kc, const float4* r, int buf){
        const int kg0 = kc*32;
        const uint32_t aB = smb + (uint32_t)(buf*STB0);
#pragma unroll
        for (int i=0;i<2;i++){
            const int idx = t + 256*i;
            const int k = idx>>4, m4 = (idx&15)*4;
            uint2 h = f4h(r[i]);
            asm volatile("st.shared.v2.b32 [%0], {%1,%2};"
                         :: "r"(aB + (uint32_t)((k*LDH + m4)*2)), "r"(h.x), "r"(h.y));
            // ---- bit-pack: nibble -> 32-edge word across 8 lanes ----
            uint32_t nib = (r[i].x!=0.f ? 1u:0u) | (r[i].y!=0.f ? 2u:0u)
                         | (r[i].z!=0.f ? 4u:0u) | (r[i].w!=0.f ? 8u:0u);
            uint32_t word = nib << (4*(lane&7));
            word |= __shfl_xor_sync(0xffffffffu, word, 1);
            word |= __shfl_xor_sync(0xffffffffu, word, 2);
            word |= __shfl_xor_sync(0xffffffffu, word, 4);
            if ((lane&7)==0){
                const int wsel = (lane&15)>>3;   // which 32-edge word of this 64-edge tile
                g_hb[((size_t)b*NN + kg0 + k)*EW + (m0g>>5) + wsel] = word;
            }
        }
    };
    auto stageB = [&](int kc, int buf){
        const int kg0 = kc*32;
        const uint32_t bB = smb + (uint32_t)(buf*STB0 + A0_BYTES);
        const __half* src0 = g_xh + ((size_t)b*NN + kg0)*CC;
#pragma unroll
        for (int i=0;i<2;i++){
            const int idx = t + 256*i;
            const int k = idx>>4, n8 = (idx&15)*8;
            cpa16(bB + (uint32_t)((k*LDH + n8)*2), src0 + (size_t)k*CC + n8);
        }
    };

    auto compute = [&](int buf){
        const uint32_t aB = smb + (uint32_t)(buf*STB0);
        const uint32_t bB = aB + (uint32_t)A0_BYTES;
#pragma unroll
        for (int s=0;s<2;s++){
            const int k0 = s*16;
            uint32_t a[2][4], bf[4][2];
#pragma unroll
            for (int mt=0;mt<2;mt++)
                ldsm4t(a[mt], aB + (uint32_t)(((k0 + a_k)*LDH + wm*32 + mt*16 + a_m0)*2));
            if (wn==0){
#pragma unroll
                for (int mt=0;mt<2;mt++){
                    dg2[mt][0] = __hadd2(dg2[mt][0], __hadd2(u2h(a[mt][0]), u2h(a[mt][2])));
                    dg2[mt][1] = __hadd2(dg2[mt][1], __hadd2(u2h(a[mt][1]), u2h(a[mt][3])));
                }
            }
#pragma unroll
            for (int p=0;p<2;p++){
                uint32_t r[4];
                ldsm4t(r, bB + (uint32_t)(((k0 + b_r)*LDH + wn*32 + p*16 + b_c)*2));
                bf[2*p  ][0]=r[0]; bf[2*p  ][1]=r[1];
                bf[2*p+1][0]=r[2]; bf[2*p+1][1]=r[3];
            }
#pragma unroll
            for (int mt=0;mt<2;mt++)
#pragma unroll
                for (int j=0;j<4;j++)
                    mma16(acc[mt][j], a[mt], bf[j]);
        }
    };

    float4 rA[2];
    ldgA(0,rA); stsA(0,rA,0); stageB(0,0); cp_commit();
    ldgA(1,rA); stsA(1,rA,1); stageB(1,1); cp_commit();
    for (int kc=0; kc<CHUNKS; kc++){
        asm volatile("cp.async.wait_group 1;" ::: "memory");
        __syncthreads();
        const bool pre = (kc+2 < CHUNKS);
        if (pre){ ldgA(kc+2,rA); stageB(kc+2,(kc+2)%3); }
        cp_commit();
        compute(kc%3);
        if (pre) stsA(kc+2,rA,(kc+2)%3);
    }
    asm volatile("cp.async.wait_group 0;" ::: "memory");
    __syncthreads();   // mainloop buffers now dead; smem reused for fc

    // ---- stage W tile [k=128][n=128] ----
    {
        const uint32_t wB = smb + FC_W_OFF;
        const __half* src0 = g_wh;
#pragma unroll
        for (int i=0;i<8;i++){
            const int idx = t + 256*i;
            const int k = idx>>4, n8 = (idx&15)*8;
            cpa16(wB + (uint32_t)((k*LDH + n8)*2), src0 + (size_t)k*CC + n8);
        }
        cp_commit();
    }

    // ---- edge degrees -> deg_s ----
#pragma unroll
    for (int mt=0;mt<2;mt++)
#pragma unroll
        for (int rh=0;rh<2;rh++){
            float2 f = __half22float2(dg2[mt][rh]);
            float v = f.x + f.y;
            v += __shfl_xor_sync(0xffffffffu, v, 1);
            v += __shfl_xor_sync(0xffffffffu, v, 2);
            if (wn==0 && tig==0)
                deg_s[wm*32+mt*16+rh*8+gid] = v;
        }
    __syncthreads();

    // ---- store normalized fp16 A-tile [m=64][k=128], stride LDFA ----
    {
        const uint32_t aS = smb + FC_A_OFF;
#pragma unroll
        for (int mt=0;mt<2;mt++)
#pragma unroll
            for (int rh=0;rh<2;rh++){
                const int row = wm*32+mt*16+rh*8+gid;
                const float d = deg_s[row];
                const float inv = (d > 0.f) ? 1.f/d : 0.f;
#pragma unroll
                for (int j=0;j<4;j++){
                    const int col = wn*32 + j*8 + tig*2;
                    __half2 h = __floats2half2_rn(acc[mt][j][rh*2]*inv, acc[mt][j][rh*2+1]*inv);
                    asm volatile("st.shared.b32 [%0], %1;"
                                 :: "r"(aS + (uint32_t)((row*LDFA + col)*2)), "r"(*(uint32_t*)&h));
                }
            }
    }
    asm volatile("cp.async.wait_group 0;" ::: "memory");
    __syncthreads();

    // ---- fc GEMM: [64 x 128] = A_sm[64 x 128] @ W[128 x 128] ----
    float fcc[2][4][4];
#pragma unroll
    for (int i=0;i<2;i++)
#pragma unroll
        for (int j=0;j<4;j++)
#pragma unroll
            for (int r=0;r<4;r++) fcc[i][j][r]=0.f;
    {
        const uint32_t aS = smb + FC_A_OFF;
        const uint32_t wB = smb + FC_W_OFF;
#pragma unroll
        for (int ks=0; ks<8; ks++){
            const int k0 = ks*16;
            uint32_t a[2][4], bf[4][2];
#pragma unroll
            for (int mt=0;mt<2;mt++)
                ldsm4(a[mt], aS + (uint32_t)(((wm*32 + mt*16 + a_r)*LDFA + k0 + a_c)*2));
#pragma unroll
            for (int p=0;p<2;p++){
                uint32_t r[4];
                ldsm4t(r, wB + (uint32_t)(((k0 + b_r)*LDH + wn*32 + p*16 + b_c)*2));
                bf[2*p  ][0]=r[0]; bf[2*p  ][1]=r[1];
                bf[2*p+1][0]=r[2]; bf[2*p+1][1]=r[3];
            }
#pragma unroll
            for (int mt=0;mt<2;mt++)
#pragma unroll
                for (int j=0;j<4;j++)
                    mma16(fcc[mt][j], a[mt], bf[j]);
        }
    }

    // ---- +bias, mask, write g_efh ----
#pragma unroll
    for (int mt=0;mt<2;mt++)
#pragma unroll
        for (int rh=0;rh<2;rh++){
            const int row = wm*32+mt*16+rh*8+gid;
            const bool on = deg_s[row] > 0.f;
#pragma unroll
            for (int j=0;j<4;j++){
                const int col = wn*32 + j*8 + tig*2;
                float v0 = on ? fcc[mt][j][rh*2  ] + bias[col]   : 0.f;
                float v1 = on ? fcc[mt][j][rh*2+1] + bias[col+1] : 0.f;
                __half2 h = __floats2half2_rn(v0, v1);
                *(uint32_t*)&g_efh[((size_t)b*EE+m0g+row)*CC + col] = *(uint32_t*)&h;
            }
        }
}

// ================= e2v: bitmask-A + cp.async-B fp16 GEMM =================
#define A_SM_BYTES (128*LDMK*2)  // single A buffer, 10240 B
#define NSTAGE 5                 // B ring stages

__global__ void __launch_bounds__(256,2)
e2v_kernel(float* __restrict__ out)
{
    constexpr int CHUNKS = EE/32;   // 64 (one 32-bit word per node per chunk)

    extern __shared__ char smraw[];
    __shared__ float deg_s[128];

    const int t=threadIdx.x, lane=t&31, wid=t>>5;
    const int b=blockIdx.y, m0g=blockIdx.x*128;
    const int wm=wid>>1, wn=wid&1, gid=lane>>2, tig=lane&3;
    const int grp=lane>>3, gj=lane&7;

    const uint32_t smb  = (uint32_t)__cvta_generic_to_shared(smraw);
    const uint32_t aSM  = smb;                        // A: [m=128][k=32] stride LDMK
    const uint32_t bSM0 = smb + A_SM_BYTES;           // B ring

    float acc[2][8][4];
#pragma unroll
    for (int i=0;i<2;i++)
#pragma unroll
        for (int j=0;j<8;j++)
#pragma unroll
            for (int r=0;r<4;r++) acc[i][j][r]=0.f;

    const int a_r = ((grp&1)?8:0) + gj;
    const int a_c = ((grp&2)?8:0);
    const int b_r = ((grp&1)?8:0) + gj;
    const int b_c = (grp>>1)*8;

    // this thread's bitmask source: row m = t>>1, half-word = t&1
    const int am   = t>>1;
    const int ahalf= t&1;
    const uint32_t* __restrict__ wsrc = g_hb + ((size_t)b*NN + m0g + am)*EW;
    int degcnt = 0;

    auto stageB = [&](int kc, int buf){
        const int kg0 = kc*32;
        const uint32_t bB = bSM0 + (uint32_t)(buf*B_BYTES);
        const __half* bsrc = g_efh + ((size_t)b*EE + kg0)*CC;
#pragma unroll
        for (int i=0;i<2;i++){
            const int idx = t + 256*i;
            const int k = idx>>4, n8 = (idx&15)*8;
            cpa16(bB + (uint32_t)((k*LDH + n8)*2), bsrc + (size_t)k*CC + n8);
        }
    };

    auto expandA = [&](uint32_t word){
        const uint32_t bits = (word >> (16*ahalf)) & 0xFFFFu;
        degcnt += __popc(bits);
        uint32_t h2[8];
#pragma unroll
        for (int p=0;p<8;p++){
            uint32_t v = (bits & (1u<<(2*p)))   ? 0x00003C00u : 0u;
            if (bits & (1u<<(2*p+1))) v |= 0x3C000000u;
            h2[p] = v;
        }
        const uint32_t d0 = aSM + (uint32_t)((am*LDMK + ahalf*16)*2);
        asm volatile("st.shared.v4.b32 [%0], {%1,%2,%3,%4};"
                     :: "r"(d0), "r"(h2[0]), "r"(h2[1]), "r"(h2[2]), "r"(h2[3]));
        asm volatile("st.shared.v4.b32 [%0], {%1,%2,%3,%4};"
                     :: "r"(d0+16), "r"(h2[4]), "r"(h2[5]), "r"(h2[6]), "r"(h2[7]));
    };

    auto compute = [&](int buf){
        const uint32_t bB = bSM0 + (uint32_t)(buf*B_BYTES);
#pragma unroll
        for (int s=0;s<2;s++){
            const int k0 = s*16;
            uint32_t a[2][4], bf[8][2];
#pragma unroll
            for (int mt=0;mt<2;mt++)
                ldsm4(a[mt], aSM + (uint32_t)(((wm*32 + mt*16 + a_r)*LDMK + k0 + a_c)*2));
#pragma unroll
            for (int p=0;p<4;p++){
                uint32_t r[4];
                ldsm4t(r, bB + (uint32_t)(((k0 + b_r)*LDH + wn*64 + p*16 + b_c)*2));
                bf[2*p  ][0]=r[0]; bf[2*p  ][1]=r[1];
                bf[2*p+1][0]=r[2]; bf[2*p+1][1]=r[3];
            }
#pragma unroll
            for (int mt=0;mt<2;mt++)
#pragma unroll
                for (int j=0;j<8;j++)
                    mma16(acc[mt][j], a[mt], bf[j]);
        }
    };

    // prologue: B ring + first word prefetch
#pragma unroll
    for (int s=0; s<NSTAGE-1; s++){
        if (s < CHUNKS) stageB(s, s);
        cp_commit();
    }
    uint32_t wcur = wsrc[0];

    for (int kc=0; kc<CHUNKS; kc++){
        asm volatile("cp.async.wait_group %0;" :: "n"(NSTAGE-2) : "memory");
        __syncthreads();                       // B(kc) visible; prior A reads done
        if (kc+NSTAGE-1 < CHUNKS) stageB(kc+NSTAGE-1, (kc+NSTAGE-1)%NSTAGE);
        cp_commit();
        expandA(wcur);                         // write A(kc)
        if (kc+1 < CHUNKS) wcur = wsrc[kc+1];  // prefetch next word (L2)
        __syncthreads();                       // A(kc) visible to all warps
        compute(kc%NSTAGE);
    }

    // node degrees: pair-reduce popc
    {
        int v = degcnt + __shfl_xor_sync(0xffffffffu, degcnt, 1);
        if ((t&1)==0) deg_s[am] = (float)v;
    }
    __syncthreads();

#pragma unroll
    for (int mt=0;mt<2;mt++)
#pragma unroll
        for (int rh=0;rh<2;rh++){
            const int row = wm*32+mt*16+rh*8+gid;
            const float d   = deg_s[row];
            const float inv = (d > 0.f) ? 1.f/d : 0.f;
#pragma unroll
            for (int j=0;j<8;j++){
                const int col = wn*64 + j*8 + tig*2;
                *(float2*)&out[((size_t)b*NN+m0g+row)*CC + col]
                    = make_float2(acc[mt][j][rh*2]*inv, acc[mt][j][rh*2+1]*inv);
            }
        }
}

// ---------------- launcher ----------------
extern "C" void kernel_launch(void* const* d_in, const int* in_sizes, int n_in,
                              void* d_out, int out_size)
{
    const float* x    = (const float*)d_in[0];
    const float* H    = (const float*)d_in[1];
    const float* W    = (const float*)d_in[2];
    const float* bias = (const float*)d_in[3];
    float* out = (float*)d_out;

    const int sm0 = 3*STB0;                        // 52224 B
    const int sm2 = A_SM_BYTES + NSTAGE*B_BYTES;   // 53760 B
    cudaFuncSetAttribute(v2e_fc_kernel, cudaFuncAttributeMaxDynamicSharedMemorySize, sm0);
    cudaFuncSetAttribute(e2v_kernel,    cudaFuncAttributeMaxDynamicSharedMemorySize, sm2);

    const int prep_blk = (BB*NN*CC/4 + CC*CC/4 + 255)/256;

    prep_kernel  <<<prep_blk, 256>>>(x, W);
    v2e_fc_kernel<<<dim3(EE/64,  BB), 256, sm0>>>(H, bias);
    e2v_kernel   <<<dim3(NN/128, BB), 256, sm2>>>(out);
}